// round 1
// baseline (speedup 1.0000x reference)
#include <cuda_runtime.h>
#include <cuda_bf16.h>
#include <cfloat>
#include <math.h>

// Problem constants
#define GCNT 8
#define NNODE 2048
#define ETOT 34816              // 32768 random + 2048 self loops, per graph
#define EALL (GCNT * ETOT)      // 278528
#define GN (GCNT * NNODE)       // 16384
#define DIN 128
#define DH 256
#define LN_EPS 1e-5f

// Scratch (static device globals — allocation-free per harness rules)
__device__ float g_T[GN * DH];
__device__ float g_P[GN * DH];
__device__ float g_h[GN * DH];
__device__ int   g_rowptr[GN + 1];
__device__ int   g_cnt[GN];
__device__ int   g_col[EALL];

// ---------------------------------------------------------------------------
// CSR build (dst-sorted adjacency), reused across all 3 layers
// ---------------------------------------------------------------------------
__global__ void zero_cnt_kernel() {
    int i = blockIdx.x * blockDim.x + threadIdx.x;
    if (i < GN) g_cnt[i] = 0;
}

__global__ void hist_kernel(const int* __restrict__ dst) {
    int e = blockIdx.x * blockDim.x + threadIdx.x;
    if (e >= EALL) return;
    int g = e / ETOT;
    int d = dst[e] + g * NNODE;
    atomicAdd(&g_cnt[d], 1);
}

// One-block exclusive scan of g_cnt[0..GN) into g_rowptr, re-zeroing g_cnt.
__global__ void scan_kernel() {
    __shared__ int sh[1024];
    int t = threadIdx.x;
    int base = t * 16;
    int local[16];
    int run = 0;
#pragma unroll
    for (int i = 0; i < 16; i++) { local[i] = run; run += g_cnt[base + i]; }
    sh[t] = run;
    __syncthreads();
    // Hillis-Steele inclusive scan over 1024 partials
    for (int d = 1; d < 1024; d <<= 1) {
        int v = (t >= d) ? sh[t - d] : 0;
        __syncthreads();
        sh[t] += v;
        __syncthreads();
    }
    int off = (t == 0) ? 0 : sh[t - 1];
#pragma unroll
    for (int i = 0; i < 16; i++) {
        g_rowptr[base + i] = off + local[i];
        g_cnt[base + i] = 0;
    }
    if (t == 1023) g_rowptr[GN] = sh[1023];
}

__global__ void fill_kernel(const int* __restrict__ src, const int* __restrict__ dst) {
    int e = blockIdx.x * blockDim.x + threadIdx.x;
    if (e >= EALL) return;
    int g = e / ETOT;
    int d = dst[e] + g * NNODE;
    int s = src[e] + g * NNODE;
    int pos = g_rowptr[d] + atomicAdd(&g_cnt[d], 1);
    g_col[pos] = s;
}

// ---------------------------------------------------------------------------
// Tiled fp32 SGEMM: C[M, 256] = A[M, K] @ W[K, 256]   (no bias; fused later)
// BM=BN=64, BK=8, 256 threads, 4x4 per-thread tile.
// M=16384 (mult of 64), K in {128, 256} (mult of 8), Ncols=256 (mult of 64).
// ---------------------------------------------------------------------------
template <int K>
__global__ __launch_bounds__(256)
void sgemm64(const float* __restrict__ A, const float* __restrict__ W,
             float* __restrict__ C) {
    __shared__ float As[8][64];
    __shared__ float Bs[8][64];
    const int row0 = blockIdx.x * 64;
    const int col0 = blockIdx.y * 64;
    const int tid = threadIdx.x;
    const int tr = tid >> 4;   // 0..15
    const int tc = tid & 15;   // 0..15

    float acc[4][4] = {};

    for (int k0 = 0; k0 < K; k0 += 8) {
        if (tid < 128) {
            // A tile: 64 rows x 8 k, as 128 float4 loads, transposed into As[k][r]
            int r  = tid >> 1;
            int kq = (tid & 1) << 2;
            float4 a = *reinterpret_cast<const float4*>(
                &A[(size_t)(row0 + r) * K + k0 + kq]);
            As[kq + 0][r] = a.x;
            As[kq + 1][r] = a.y;
            As[kq + 2][r] = a.z;
            As[kq + 3][r] = a.w;
        } else {
            // B tile: 8 k x 64 cols, as 128 float4 loads
            int li = tid - 128;
            int k  = li >> 4;
            int cq = (li & 15) << 2;
            float4 b = *reinterpret_cast<const float4*>(
                &W[(size_t)(k0 + k) * DH + col0 + cq]);
            *reinterpret_cast<float4*>(&Bs[k][cq]) = b;
        }
        __syncthreads();
#pragma unroll
        for (int k = 0; k < 8; k++) {
            float4 a4 = *reinterpret_cast<const float4*>(&As[k][tr * 4]);
            float4 b4 = *reinterpret_cast<const float4*>(&Bs[k][tc * 4]);
            float a[4] = {a4.x, a4.y, a4.z, a4.w};
            float b[4] = {b4.x, b4.y, b4.z, b4.w};
#pragma unroll
            for (int i = 0; i < 4; i++)
#pragma unroll
                for (int j = 0; j < 4; j++) acc[i][j] += a[i] * b[j];
        }
        __syncthreads();
    }

#pragma unroll
    for (int i = 0; i < 4; i++) {
        float4 o = make_float4(acc[i][0], acc[i][1], acc[i][2], acc[i][3]);
        *reinterpret_cast<float4*>(
            &C[(size_t)(row0 + tr * 4 + i) * DH + col0 + tc * 4]) = o;
    }
}

// ---------------------------------------------------------------------------
// Fused per-node: gather-min over src neighbors + combine + LayerNorm + ELU
// grid = GN blocks, block = 256 threads (one per channel)
// ---------------------------------------------------------------------------
__global__ __launch_bounds__(DH)
void fuse_kernel(const float* __restrict__ T, const float* __restrict__ P,
                 const float* __restrict__ bt, const float* __restrict__ bp,
                 const float* __restrict__ gam, const float* __restrict__ bet,
                 float* __restrict__ out) {
    const int v = blockIdx.x;
    const int ch = threadIdx.x;
    const int beg = g_rowptr[v];
    const int end = g_rowptr[v + 1];

    float m0 = FLT_MAX, m1 = FLT_MAX, m2 = FLT_MAX, m3 = FLT_MAX;
    int e = beg;
    for (; e + 4 <= end; e += 4) {
        int s0 = g_col[e + 0];
        int s1 = g_col[e + 1];
        int s2 = g_col[e + 2];
        int s3 = g_col[e + 3];
        m0 = fminf(m0, T[(size_t)s0 * DH + ch]);
        m1 = fminf(m1, T[(size_t)s1 * DH + ch]);
        m2 = fminf(m2, T[(size_t)s2 * DH + ch]);
        m3 = fminf(m3, T[(size_t)s3 * DH + ch]);
    }
    for (; e < end; e++) m0 = fminf(m0, T[(size_t)g_col[e] * DH + ch]);
    float mn = fminf(fminf(m0, m1), fminf(m2, m3));

    float val = T[(size_t)v * DH + ch] + P[(size_t)v * DH + ch]
              + bt[ch] + bp[ch] - mn;

    // Two-pass LayerNorm over the 256 channels (matches reference math)
    __shared__ float red[8];
    const int lane = threadIdx.x & 31;
    const int wrp  = threadIdx.x >> 5;

    float s = val;
#pragma unroll
    for (int o = 16; o; o >>= 1) s += __shfl_xor_sync(0xffffffffu, s, o);
    if (lane == 0) red[wrp] = s;
    __syncthreads();
    float tot = red[0] + red[1] + red[2] + red[3]
              + red[4] + red[5] + red[6] + red[7];
    float mu = tot * (1.0f / DH);
    __syncthreads();

    float d = val - mu;
    float s2 = d * d;
#pragma unroll
    for (int o = 16; o; o >>= 1) s2 += __shfl_xor_sync(0xffffffffu, s2, o);
    if (lane == 0) red[wrp] = s2;
    __syncthreads();
    float var = (red[0] + red[1] + red[2] + red[3]
               + red[4] + red[5] + red[6] + red[7]) * (1.0f / DH);

    float y = d * rsqrtf(var + LN_EPS) * gam[ch] + bet[ch];
    out[(size_t)v * DH + ch] = (y > 0.0f) ? y : expm1f(y);
}

// ---------------------------------------------------------------------------
extern "C" void kernel_launch(void* const* d_in, const int* in_sizes, int n_in,
                              void* d_out, int out_size) {
    const float* x   = (const float*)d_in[0];
    const float* Wt0 = (const float*)d_in[1];
    const float* bt0 = (const float*)d_in[2];
    const float* Wp0 = (const float*)d_in[3];
    const float* bp0 = (const float*)d_in[4];
    const float* g0  = (const float*)d_in[5];
    const float* b0  = (const float*)d_in[6];
    const float* Wt1 = (const float*)d_in[7];
    const float* bt1 = (const float*)d_in[8];
    const float* Wp1 = (const float*)d_in[9];
    const float* bp1 = (const float*)d_in[10];
    const float* g1  = (const float*)d_in[11];
    const float* b1  = (const float*)d_in[12];
    const float* Wt2 = (const float*)d_in[13];
    const float* bt2 = (const float*)d_in[14];
    const float* Wp2 = (const float*)d_in[15];
    const float* bp2 = (const float*)d_in[16];
    const float* g2  = (const float*)d_in[17];
    const float* b2  = (const float*)d_in[18];
    const int*   src = (const int*)d_in[19];
    const int*   dst = (const int*)d_in[20];
    float* out = (float*)d_out;

    float* Tp;  cudaGetSymbolAddress((void**)&Tp, g_T);
    float* Pp;  cudaGetSymbolAddress((void**)&Pp, g_P);
    float* hp;  cudaGetSymbolAddress((void**)&hp, g_h);

    // CSR build (dst adjacency, shared by all layers)
    zero_cnt_kernel<<<GN / 256, 256>>>();
    hist_kernel<<<EALL / 256, 256>>>(dst);
    scan_kernel<<<1, 1024>>>();
    fill_kernel<<<EALL / 256, 256>>>(src, dst);

    dim3 ggrid(GN / 64, DH / 64);

    // Layer 0 (K = DIN = 128), input x
    sgemm64<DIN><<<ggrid, 256>>>(x, Wt0, Tp);
    sgemm64<DIN><<<ggrid, 256>>>(x, Wp0, Pp);
    fuse_kernel<<<GN, DH>>>(Tp, Pp, bt0, bp0, g0, b0, hp);

    // Layer 1 (K = DH = 256), input g_h
    sgemm64<DH><<<ggrid, 256>>>(hp, Wt1, Tp);
    sgemm64<DH><<<ggrid, 256>>>(hp, Wp1, Pp);
    fuse_kernel<<<GN, DH>>>(Tp, Pp, bt1, bp1, g1, b1, hp);

    // Layer 2 (K = DH = 256), input g_h, write final output
    sgemm64<DH><<<ggrid, 256>>>(hp, Wt2, Tp);
    sgemm64<DH><<<ggrid, 256>>>(hp, Wp2, Pp);
    fuse_kernel<<<GN, DH>>>(Tp, Pp, bt2, bp2, g2, b2, out);
}

// round 3
// speedup vs baseline: 1.5868x; 1.5868x over previous
#include <cuda_runtime.h>
#include <cuda_bf16.h>
#include <cfloat>
#include <math.h>
#include <cstdint>

// Problem constants
#define GCNT 8
#define NNODE 2048
#define ETOT 34816              // 32768 random + 2048 self loops, per graph
#define EALL (GCNT * ETOT)      // 278528
#define GN (GCNT * NNODE)       // 16384
#define DIN 128
#define DH 256
#define LN_EPS 1e-5f

// ---------------------------------------------------------------------------
// Scratch (static device globals — allocation-free per harness rules)
// ---------------------------------------------------------------------------
__device__ float         g_T[GN * DH];
__device__ float         g_P[GN * DH];
__device__ __nv_bfloat16 g_Ahi[GN * DH];     // activations hi (layer0: [GN x 128])
__device__ __nv_bfloat16 g_Alo[GN * DH];     // activations lo
__device__ __nv_bfloat16 g_Bhi[512 * DH];    // concat(Wt,Wp) as [n=512][k=K]
__device__ __nv_bfloat16 g_Blo[512 * DH];
__device__ int g_rowptr[GN + 1];
__device__ int g_cnt[GN];
__device__ int g_col[EALL];

// ---------------------------------------------------------------------------
// CSR build (dst-sorted adjacency), reused across all 3 layers
// ---------------------------------------------------------------------------
__global__ void zero_cnt_kernel() {
    int i = blockIdx.x * blockDim.x + threadIdx.x;
    if (i < GN) g_cnt[i] = 0;
}

__global__ void hist_kernel(const int* __restrict__ dst) {
    int e = blockIdx.x * blockDim.x + threadIdx.x;
    if (e >= EALL) return;
    int g = e / ETOT;
    int d = dst[e] + g * NNODE;
    atomicAdd(&g_cnt[d], 1);
}

__global__ void scan_kernel() {
    __shared__ int sh[1024];
    int t = threadIdx.x;
    int base = t * 16;
    int local[16];
    int run = 0;
#pragma unroll
    for (int i = 0; i < 16; i++) { local[i] = run; run += g_cnt[base + i]; }
    sh[t] = run;
    __syncthreads();
    for (int d = 1; d < 1024; d <<= 1) {
        int v = (t >= d) ? sh[t - d] : 0;
        __syncthreads();
        sh[t] += v;
        __syncthreads();
    }
    int off = (t == 0) ? 0 : sh[t - 1];
#pragma unroll
    for (int i = 0; i < 16; i++) {
        g_rowptr[base + i] = off + local[i];
        g_cnt[base + i] = 0;
    }
    if (t == 1023) g_rowptr[GN] = sh[1023];
}

__global__ void fill_kernel(const int* __restrict__ src, const int* __restrict__ dst) {
    int e = blockIdx.x * blockDim.x + threadIdx.x;
    if (e >= EALL) return;
    int g = e / ETOT;
    int d = dst[e] + g * NNODE;
    int s = src[e] + g * NNODE;
    int pos = g_rowptr[d] + atomicAdd(&g_cnt[d], 1);
    g_col[pos] = s;
}

// ---------------------------------------------------------------------------
// Conversions to split-bf16
// ---------------------------------------------------------------------------
__global__ void xconv_kernel(const float* __restrict__ x) {
    int i = blockIdx.x * blockDim.x + threadIdx.x;   // over GN*DIN
    float v = x[i];
    __nv_bfloat16 hi = __float2bfloat16(v);
    g_Ahi[i] = hi;
    g_Alo[i] = __float2bfloat16(v - __bfloat162float(hi));
}

template <int K>
__global__ void wconv_kernel(const float* __restrict__ Wt, const float* __restrict__ Wp) {
    int idx = blockIdx.x * blockDim.x + threadIdx.x;  // over 512*K
    if (idx >= 512 * K) return;
    int n = idx / K;
    int k = idx - n * K;
    float v = (n < 256) ? Wt[k * 256 + n] : Wp[k * 256 + (n - 256)];
    __nv_bfloat16 hi = __float2bfloat16(v);
    g_Bhi[idx] = hi;
    g_Blo[idx] = __float2bfloat16(v - __bfloat162float(hi));
}

// ---------------------------------------------------------------------------
// mma.sync helpers (sm_80+ path — works on plain compute_100 target)
// ---------------------------------------------------------------------------
static __device__ __forceinline__ uint32_t s2u(const void* p) {
    uint32_t a;
    asm("{ .reg .u64 t; cvta.to.shared.u64 t, %1; cvt.u32.u64 %0, t; }"
        : "=r"(a) : "l"(p));
    return a;
}

static __device__ __forceinline__ void ldm_x4(uint32_t* r, uint32_t saddr) {
    asm volatile("ldmatrix.sync.aligned.m8n8.x4.shared.b16 {%0,%1,%2,%3}, [%4];"
        : "=r"(r[0]), "=r"(r[1]), "=r"(r[2]), "=r"(r[3]) : "r"(saddr));
}

static __device__ __forceinline__ void mma16816(float* c, const uint32_t* a,
                                                const uint32_t* b) {
    asm volatile(
        "mma.sync.aligned.m16n8k16.row.col.f32.bf16.bf16.f32 "
        "{%0,%1,%2,%3}, {%4,%5,%6,%7}, {%8,%9}, {%0,%1,%2,%3};"
        : "+f"(c[0]), "+f"(c[1]), "+f"(c[2]), "+f"(c[3])
        : "r"(a[0]), "r"(a[1]), "r"(a[2]), "r"(a[3]), "r"(b[0]), "r"(b[1]));
}

// ---------------------------------------------------------------------------
// Tensor-core GEMM (split-bf16, 3-term): C[GN, 512] = A[GN, K] @ B[512, K]^T
//   C cols [0,256) -> g_T, [256,512) -> g_P
// grid = (GN/128, 4), 256 threads. CTA tile 128x128, warp tile 64x32.
// SMEM tiles stride 40 bf16 (80B): conflict-free for 16B ldmatrix rows.
// ---------------------------------------------------------------------------
#define ASTR 40

template <int K>
__global__ __launch_bounds__(256)
void gemm_mma() {
    __shared__ __align__(16) __nv_bfloat16 sAh[128 * ASTR];
    __shared__ __align__(16) __nv_bfloat16 sAl[128 * ASTR];
    __shared__ __align__(16) __nv_bfloat16 sBh[128 * ASTR];
    __shared__ __align__(16) __nv_bfloat16 sBl[128 * ASTR];

    const int tid  = threadIdx.x;
    const int wid  = tid >> 5;
    const int lane = tid & 31;
    const int wm = wid >> 2;          // 0..1
    const int wn = wid & 3;           // 0..3
    const int row0 = blockIdx.x * 128;
    const int by   = blockIdx.y;      // 0..3  -> C cols [by*128, by*128+128)
    const int n0   = by * 128;

    float acc[4][4][4] = {};

    // Per-thread ldmatrix base byte addresses
    const uint32_t aOffB = (uint32_t)(((wm * 64 + (lane & 15)) * ASTR
                                       + ((lane >> 4) << 3)) * 2);
    const uint32_t bOffB = (uint32_t)(((wn * 32 + ((lane >> 4) << 3) + (lane & 7)) * ASTR
                                       + (((lane >> 3) & 1) << 3)) * 2);
    const uint32_t aH = s2u(sAh) + aOffB;
    const uint32_t aL = s2u(sAl) + aOffB;
    const uint32_t bH = s2u(sBh) + bOffB;
    const uint32_t bL = s2u(sBl) + bOffB;

    constexpr int NCH = K / 32;
    for (int c = 0; c < NCH; c++) {
        const int k0 = c * 32;
        // Stage tiles: 128 rows x 32 bf16 each (2 x uint4 per thread per tile)
#pragma unroll
        for (int it = 0; it < 2; it++) {
            int idx = it * 256 + tid;
            int r = idx >> 2;
            int q = idx & 3;
            int so = r * ASTR + q * 8;
            size_t ga = (size_t)(row0 + r) * K + k0 + q * 8;
            size_t gb = (size_t)(n0 + r) * K + k0 + q * 8;
            *(uint4*)&sAh[so] = *(const uint4*)&g_Ahi[ga];
            *(uint4*)&sAl[so] = *(const uint4*)&g_Alo[ga];
            *(uint4*)&sBh[so] = *(const uint4*)&g_Bhi[gb];
            *(uint4*)&sBl[so] = *(const uint4*)&g_Blo[gb];
        }
        __syncthreads();

#pragma unroll
        for (int s = 0; s < 2; s++) {
            const uint32_t sk = (uint32_t)(s * 32);   // +16 k-elems = 32 bytes
            uint32_t ah[4][4], al[4][4], bh[2][4], bl[2][4];
#pragma unroll
            for (int mt = 0; mt < 4; mt++) {
                ldm_x4(ah[mt], aH + mt * (16 * ASTR * 2) + sk);
                ldm_x4(al[mt], aL + mt * (16 * ASTR * 2) + sk);
            }
#pragma unroll
            for (int p = 0; p < 2; p++) {
                ldm_x4(bh[p], bH + p * (16 * ASTR * 2) + sk);
                ldm_x4(bl[p], bL + p * (16 * ASTR * 2) + sk);
            }
#pragma unroll
            for (int mt = 0; mt < 4; mt++)
#pragma unroll
                for (int nt = 0; nt < 4; nt++) {
                    const uint32_t* Bh = &bh[nt >> 1][(nt & 1) * 2];
                    const uint32_t* Bl = &bl[nt >> 1][(nt & 1) * 2];
                    mma16816(acc[mt][nt], ah[mt], Bh);
                    mma16816(acc[mt][nt], ah[mt], Bl);
                    mma16816(acc[mt][nt], al[mt], Bh);
                }
        }
        __syncthreads();
    }

    // Epilogue: cols [0,256) of C -> g_T, [256,512) -> g_P
    float* __restrict__ outp = (by < 2) ? g_T : g_P;
    const int col0 = (by & 1) * 128 + wn * 32;
    const int g  = lane >> 2;
    const int tg = lane & 3;
#pragma unroll
    for (int mt = 0; mt < 4; mt++) {
        int r = row0 + wm * 64 + mt * 16 + g;
#pragma unroll
        for (int nt = 0; nt < 4; nt++) {
            int cc = col0 + nt * 8 + tg * 2;
            *(float2*)&outp[(size_t)r * DH + cc] =
                make_float2(acc[mt][nt][0], acc[mt][nt][1]);
            *(float2*)&outp[(size_t)(r + 8) * DH + cc] =
                make_float2(acc[mt][nt][2], acc[mt][nt][3]);
        }
    }
}

// ---------------------------------------------------------------------------
// Fused per-node: gather-min over src neighbors + combine + LayerNorm + ELU
// grid = GN blocks, block = 256 threads (one per channel).
// LAST: write fp32 to out;  else: write split-bf16 into g_Ahi/g_Alo.
// ---------------------------------------------------------------------------
template <bool LAST>
__global__ __launch_bounds__(DH)
void fuse_kernel(const float* __restrict__ bt, const float* __restrict__ bp,
                 const float* __restrict__ gam, const float* __restrict__ bet,
                 float* __restrict__ out) {
    const int v = blockIdx.x;
    const int ch = threadIdx.x;
    const int beg = g_rowptr[v];
    const int end = g_rowptr[v + 1];

    float m0 = FLT_MAX, m1 = FLT_MAX, m2 = FLT_MAX, m3 = FLT_MAX;
    int e = beg;
    for (; e + 4 <= end; e += 4) {
        int s0 = g_col[e + 0];
        int s1 = g_col[e + 1];
        int s2 = g_col[e + 2];
        int s3 = g_col[e + 3];
        m0 = fminf(m0, g_T[(size_t)s0 * DH + ch]);
        m1 = fminf(m1, g_T[(size_t)s1 * DH + ch]);
        m2 = fminf(m2, g_T[(size_t)s2 * DH + ch]);
        m3 = fminf(m3, g_T[(size_t)s3 * DH + ch]);
    }
    for (; e < end; e++) m0 = fminf(m0, g_T[(size_t)g_col[e] * DH + ch]);
    float mn = fminf(fminf(m0, m1), fminf(m2, m3));

    float val = g_T[(size_t)v * DH + ch] + g_P[(size_t)v * DH + ch]
              + bt[ch] + bp[ch] - mn;

    __shared__ float red[8];
    const int lane = threadIdx.x & 31;
    const int wrp  = threadIdx.x >> 5;

    float s = val;
#pragma unroll
    for (int o = 16; o; o >>= 1) s += __shfl_xor_sync(0xffffffffu, s, o);
    if (lane == 0) red[wrp] = s;
    __syncthreads();
    float tot = red[0] + red[1] + red[2] + red[3]
              + red[4] + red[5] + red[6] + red[7];
    float mu = tot * (1.0f / DH);
    __syncthreads();

    float d = val - mu;
    float s2 = d * d;
#pragma unroll
    for (int o = 16; o; o >>= 1) s2 += __shfl_xor_sync(0xffffffffu, s2, o);
    if (lane == 0) red[wrp] = s2;
    __syncthreads();
    float var = (red[0] + red[1] + red[2] + red[3]
               + red[4] + red[5] + red[6] + red[7]) * (1.0f / DH);

    float y = d * rsqrtf(var + LN_EPS) * gam[ch] + bet[ch];
    float act = (y > 0.0f) ? y : expm1f(y);

    if (LAST) {
        out[(size_t)v * DH + ch] = act;
    } else {
        __nv_bfloat16 hi = __float2bfloat16(act);
        g_Ahi[(size_t)v * DH + ch] = hi;
        g_Alo[(size_t)v * DH + ch] = __float2bfloat16(act - __bfloat162float(hi));
    }
}

// ---------------------------------------------------------------------------
extern "C" void kernel_launch(void* const* d_in, const int* in_sizes, int n_in,
                              void* d_out, int out_size) {
    const float* x   = (const float*)d_in[0];
    const float* Wt0 = (const float*)d_in[1];
    const float* bt0 = (const float*)d_in[2];
    const float* Wp0 = (const float*)d_in[3];
    const float* bp0 = (const float*)d_in[4];
    const float* g0  = (const float*)d_in[5];
    const float* b0  = (const float*)d_in[6];
    const float* Wt1 = (const float*)d_in[7];
    const float* bt1 = (const float*)d_in[8];
    const float* Wp1 = (const float*)d_in[9];
    const float* bp1 = (const float*)d_in[10];
    const float* g1  = (const float*)d_in[11];
    const float* b1  = (const float*)d_in[12];
    const float* Wt2 = (const float*)d_in[13];
    const float* bt2 = (const float*)d_in[14];
    const float* Wp2 = (const float*)d_in[15];
    const float* bp2 = (const float*)d_in[16];
    const float* g2  = (const float*)d_in[17];
    const float* b2  = (const float*)d_in[18];
    const int*   src = (const int*)d_in[19];
    const int*   dst = (const int*)d_in[20];
    float* out = (float*)d_out;

    // CSR build (dst adjacency, shared by all layers)
    zero_cnt_kernel<<<GN / 256, 256>>>();
    hist_kernel<<<EALL / 256, 256>>>(dst);
    scan_kernel<<<1, 1024>>>();
    fill_kernel<<<EALL / 256, 256>>>(src, dst);

    // Split input into bf16 hi/lo
    xconv_kernel<<<(GN * DIN) / 256, 256>>>(x);

    dim3 ggrid(GN / 128, 4);

    // Layer 0 (K = 128)
    wconv_kernel<DIN><<<(512 * DIN) / 256, 256>>>(Wt0, Wp0);
    gemm_mma<DIN><<<ggrid, 256>>>();
    fuse_kernel<false><<<GN, DH>>>(bt0, bp0, g0, b0, nullptr);

    // Layer 1 (K = 256)
    wconv_kernel<DH><<<(512 * DH) / 256, 256>>>(Wt1, Wp1);
    gemm_mma<DH><<<ggrid, 256>>>();
    fuse_kernel<false><<<GN, DH>>>(bt1, bp1, g1, b1, nullptr);

    // Layer 2 (K = 256), final output fp32
    wconv_kernel<DH><<<(512 * DH) / 256, 256>>>(Wt2, Wp2);
    gemm_mma<DH><<<ggrid, 256>>>();
    fuse_kernel<true><<<GN, DH>>>(bt2, bp2, g2, b2, out);
}

// round 5
// speedup vs baseline: 1.5983x; 1.0073x over previous
#include <cuda_runtime.h>
#include <cuda_bf16.h>
#include <cfloat>
#include <math.h>
#include <cstdint>

// Problem constants
#define GCNT 8
#define NNODE 2048
#define ETOT 34816              // 32768 random + 2048 self loops, per graph
#define EALL (GCNT * ETOT)      // 278528
#define GN (GCNT * NNODE)       // 16384
#define DIN 128
#define DH 256
#define LN_EPS 1e-5f

// ---------------------------------------------------------------------------
// Scratch (static device globals — allocation-free per harness rules)
// ---------------------------------------------------------------------------
__device__ float         g_T[GN * DH];
__device__ float         g_P[GN * DH];
__device__ __nv_bfloat16 g_Ahi[GN * DH];     // activations hi (layer0: [GN x 128])
__device__ __nv_bfloat16 g_Alo[GN * DH];     // activations lo
__device__ __nv_bfloat16 g_Bhi[512 * DH];    // concat(Wt,Wp) as [n=512][k=K]
__device__ __nv_bfloat16 g_Blo[512 * DH];
__device__ int g_rowptr[GN + 1];
__device__ int g_cnt[GN];
__device__ int g_col[EALL];

// ---------------------------------------------------------------------------
// CSR build (dst-sorted adjacency), reused across all 3 layers
// ---------------------------------------------------------------------------
__global__ void zero_cnt_kernel() {
    int i = blockIdx.x * blockDim.x + threadIdx.x;
    if (i < GN) g_cnt[i] = 0;
}

__global__ void hist_kernel(const int* __restrict__ dst) {
    int e = blockIdx.x * blockDim.x + threadIdx.x;
    if (e >= EALL) return;
    int g = e / ETOT;
    int d = dst[e] + g * NNODE;
    atomicAdd(&g_cnt[d], 1);
}

__global__ void scan_kernel() {
    __shared__ int sh[1024];
    int t = threadIdx.x;
    int base = t * 16;
    int local[16];
    int run = 0;
#pragma unroll
    for (int i = 0; i < 16; i++) { local[i] = run; run += g_cnt[base + i]; }
    sh[t] = run;
    __syncthreads();
    for (int d = 1; d < 1024; d <<= 1) {
        int v = (t >= d) ? sh[t - d] : 0;
        __syncthreads();
        sh[t] += v;
        __syncthreads();
    }
    int off = (t == 0) ? 0 : sh[t - 1];
#pragma unroll
    for (int i = 0; i < 16; i++) {
        g_rowptr[base + i] = off + local[i];
        g_cnt[base + i] = 0;
    }
    if (t == 1023) g_rowptr[GN] = sh[1023];
}

__global__ void fill_kernel(const int* __restrict__ src, const int* __restrict__ dst) {
    int e = blockIdx.x * blockDim.x + threadIdx.x;
    if (e >= EALL) return;
    int g = e / ETOT;
    int d = dst[e] + g * NNODE;
    int s = src[e] + g * NNODE;
    int pos = g_rowptr[d] + atomicAdd(&g_cnt[d], 1);
    g_col[pos] = s;
}

// ---------------------------------------------------------------------------
// Conversions to split-bf16
// ---------------------------------------------------------------------------
__global__ void xconv_kernel(const float* __restrict__ x) {
    int i = blockIdx.x * blockDim.x + threadIdx.x;   // over GN*DIN
    float v = x[i];
    __nv_bfloat16 hi = __float2bfloat16(v);
    g_Ahi[i] = hi;
    g_Alo[i] = __float2bfloat16(v - __bfloat162float(hi));
}

template <int K>
__global__ void wconv_kernel(const float* __restrict__ Wt, const float* __restrict__ Wp) {
    int idx = blockIdx.x * blockDim.x + threadIdx.x;  // over 512*K
    if (idx >= 512 * K) return;
    int n = idx / K;
    int k = idx - n * K;
    float v = (n < 256) ? Wt[k * 256 + n] : Wp[k * 256 + (n - 256)];
    __nv_bfloat16 hi = __float2bfloat16(v);
    g_Bhi[idx] = hi;
    g_Blo[idx] = __float2bfloat16(v - __bfloat162float(hi));
}

// ---------------------------------------------------------------------------
// mma.sync helpers (sm_80+ path — works on plain compute_100 target)
// ---------------------------------------------------------------------------
static __device__ __forceinline__ uint32_t s2u(const void* p) {
    uint32_t a;
    asm("{ .reg .u64 t; cvta.to.shared.u64 t, %1; cvt.u32.u64 %0, t; }"
        : "=r"(a) : "l"(p));
    return a;
}

static __device__ __forceinline__ void ldm_x4(uint32_t* r, uint32_t saddr) {
    asm volatile("ldmatrix.sync.aligned.m8n8.x4.shared.b16 {%0,%1,%2,%3}, [%4];"
        : "=r"(r[0]), "=r"(r[1]), "=r"(r[2]), "=r"(r[3]) : "r"(saddr));
}

static __device__ __forceinline__ void mma16816(float* c, const uint32_t* a,
                                                const uint32_t* b) {
    asm volatile(
        "mma.sync.aligned.m16n8k16.row.col.f32.bf16.bf16.f32 "
        "{%0,%1,%2,%3}, {%4,%5,%6,%7}, {%8,%9}, {%0,%1,%2,%3};"
        : "+f"(c[0]), "+f"(c[1]), "+f"(c[2]), "+f"(c[3])
        : "r"(a[0]), "r"(a[1]), "r"(a[2]), "r"(a[3]), "r"(b[0]), "r"(b[1]));
}

static __device__ __forceinline__ void cp16(uint32_t s, const void* g) {
    asm volatile("cp.async.cg.shared.global [%0], [%1], 16;" :: "r"(s), "l"(g));
}
#define CP_COMMIT() asm volatile("cp.async.commit_group;" ::: "memory")
#define CP_WAIT(N)  asm volatile("cp.async.wait_group %0;" :: "n"(N) : "memory")

// ---------------------------------------------------------------------------
// Tensor-core GEMM (split-bf16, 3-term): C[GN, 512] = A[GN, K] @ B[512, K]^T
//   C cols [0,256) -> g_T, [256,512) -> g_P
// grid = (GN/128, 4), 256 threads. CTA tile 128x128, warp tile 64x32.
// 2-stage cp.async pipeline; SMEM tiles stride 40 bf16, conflict-free ldmatrix.
// ---------------------------------------------------------------------------
#define ASTR 40
#define TILEB (128 * ASTR * 2)          // 10240 B per tile
#define STAGEB (4 * TILEB)              // Ah, Al, Bh, Bl
#define GEMM_SMEM (2 * STAGEB)          // 81920 B

template <int K>
__global__ __launch_bounds__(256)
void gemm_mma() {
    extern __shared__ __align__(16) char dsm[];
    const uint32_t sbase = s2u(dsm);

    const int tid  = threadIdx.x;
    const int wid  = tid >> 5;
    const int lane = tid & 31;
    const int wm = wid >> 2;          // 0..1
    const int wn = wid & 3;           // 0..3
    const int row0 = blockIdx.x * 128;
    const int by   = blockIdx.y;      // 0..3  -> C cols [by*128, by*128+128)
    const int n0   = by * 128;

    float acc[4][4][4] = {};

    // Staging geometry (per thread, 2 iters x 4 tiles x 16B)
    const int r0s = tid >> 2;                 // it=0 row
    const int q0s = tid & 3;
    const uint32_t soff0 = (uint32_t)((r0s * ASTR + q0s * 8) * 2);
    const uint32_t soff1 = (uint32_t)(((r0s + 64) * ASTR + q0s * 8) * 2);

    // ldmatrix per-thread base byte offsets
    const uint32_t aOffB = (uint32_t)(((wm * 64 + (lane & 15)) * ASTR
                                       + ((lane >> 4) << 3)) * 2);
    const uint32_t bOffB = (uint32_t)(((wn * 32 + ((lane >> 4) << 3) + (lane & 7)) * ASTR
                                       + (((lane >> 3) & 1) << 3)) * 2);

    constexpr int NCH = K / 32;

    auto issue = [&](int c, int stage) {
        const int k0 = c * 32;
        const uint32_t sb = sbase + stage * STAGEB;
        {
            size_t ga = (size_t)(row0 + r0s) * K + k0 + q0s * 8;
            size_t gb = (size_t)(n0 + r0s) * K + k0 + q0s * 8;
            cp16(sb + 0 * TILEB + soff0, g_Ahi + ga);
            cp16(sb + 1 * TILEB + soff0, g_Alo + ga);
            cp16(sb + 2 * TILEB + soff0, g_Bhi + gb);
            cp16(sb + 3 * TILEB + soff0, g_Blo + gb);
        }
        {
            size_t ga = (size_t)(row0 + 64 + r0s) * K + k0 + q0s * 8;
            size_t gb = (size_t)(n0 + 64 + r0s) * K + k0 + q0s * 8;
            cp16(sb + 0 * TILEB + soff1, g_Ahi + ga);
            cp16(sb + 1 * TILEB + soff1, g_Alo + ga);
            cp16(sb + 2 * TILEB + soff1, g_Bhi + gb);
            cp16(sb + 3 * TILEB + soff1, g_Blo + gb);
        }
        CP_COMMIT();
    };

    issue(0, 0);

    for (int c = 0; c < NCH; c++) {
        const int cur = c & 1;
        if (c + 1 < NCH) {
            issue(c + 1, cur ^ 1);
            CP_WAIT(1);
        } else {
            CP_WAIT(0);
        }
        __syncthreads();

        const uint32_t sb = sbase + cur * STAGEB;
        const uint32_t aH = sb + 0 * TILEB + aOffB;
        const uint32_t aL = sb + 1 * TILEB + aOffB;
        const uint32_t bH = sb + 2 * TILEB + bOffB;
        const uint32_t bL = sb + 3 * TILEB + bOffB;

#pragma unroll
        for (int s = 0; s < 2; s++) {
            const uint32_t sk = (uint32_t)(s * 32);   // +16 k-elems = 32 bytes
            uint32_t ah[4][4], al[4][4], bh[2][4], bl[2][4];
#pragma unroll
            for (int mt = 0; mt < 4; mt++) {
                ldm_x4(ah[mt], aH + mt * (16 * ASTR * 2) + sk);
                ldm_x4(al[mt], aL + mt * (16 * ASTR * 2) + sk);
            }
#pragma unroll
            for (int p = 0; p < 2; p++) {
                ldm_x4(bh[p], bH + p * (16 * ASTR * 2) + sk);
                ldm_x4(bl[p], bL + p * (16 * ASTR * 2) + sk);
            }
#pragma unroll
            for (int mt = 0; mt < 4; mt++)
#pragma unroll
                for (int nt = 0; nt < 4; nt++) {
                    const uint32_t* Bh = &bh[nt >> 1][(nt & 1) * 2];
                    const uint32_t* Bl = &bl[nt >> 1][(nt & 1) * 2];
                    mma16816(acc[mt][nt], ah[mt], Bh);
                    mma16816(acc[mt][nt], ah[mt], Bl);
                    mma16816(acc[mt][nt], al[mt], Bh);
                }
        }
        __syncthreads();
    }

    // Epilogue: cols [0,256) of C -> g_T, [256,512) -> g_P
    float* __restrict__ outp = (by < 2) ? g_T : g_P;
    const int col0 = (by & 1) * 128 + wn * 32;
    const int g  = lane >> 2;
    const int tg = lane & 3;
#pragma unroll
    for (int mt = 0; mt < 4; mt++) {
        int r = row0 + wm * 64 + mt * 16 + g;
#pragma unroll
        for (int nt = 0; nt < 4; nt++) {
            int cc = col0 + nt * 8 + tg * 2;
            *(float2*)&outp[(size_t)r * DH + cc] =
                make_float2(acc[mt][nt][0], acc[mt][nt][1]);
            *(float2*)&outp[(size_t)(r + 8) * DH + cc] =
                make_float2(acc[mt][nt][2], acc[mt][nt][3]);
        }
    }
}

// ---------------------------------------------------------------------------
// Fused per-node: gather-min over src neighbors + combine + LayerNorm + ELU
// grid = GN blocks, block = 256 threads (one per channel).
// LAST: write fp32 to out;  else: write split-bf16 into g_Ahi/g_Alo.
// ---------------------------------------------------------------------------
template <bool LAST>
__global__ __launch_bounds__(DH)
void fuse_kernel(const float* __restrict__ bt, const float* __restrict__ bp,
                 const float* __restrict__ gam, const float* __restrict__ bet,
                 float* __restrict__ out) {
    const int v = blockIdx.x;
    const int ch = threadIdx.x;
    const int beg = g_rowptr[v];
    const int end = g_rowptr[v + 1];

    float m0 = FLT_MAX, m1 = FLT_MAX, m2 = FLT_MAX, m3 = FLT_MAX;
    int e = beg;
    for (; e + 4 <= end; e += 4) {
        int s0 = g_col[e + 0];
        int s1 = g_col[e + 1];
        int s2 = g_col[e + 2];
        int s3 = g_col[e + 3];
        m0 = fminf(m0, g_T[(size_t)s0 * DH + ch]);
        m1 = fminf(m1, g_T[(size_t)s1 * DH + ch]);
        m2 = fminf(m2, g_T[(size_t)s2 * DH + ch]);
        m3 = fminf(m3, g_T[(size_t)s3 * DH + ch]);
    }
    for (; e < end; e++) m0 = fminf(m0, g_T[(size_t)g_col[e] * DH + ch]);
    float mn = fminf(fminf(m0, m1), fminf(m2, m3));

    float val = g_T[(size_t)v * DH + ch] + g_P[(size_t)v * DH + ch]
              + bt[ch] + bp[ch] - mn;

    __shared__ float red[8];
    const int lane = threadIdx.x & 31;
    const int wrp  = threadIdx.x >> 5;

    float s = val;
#pragma unroll
    for (int o = 16; o; o >>= 1) s += __shfl_xor_sync(0xffffffffu, s, o);
    if (lane == 0) red[wrp] = s;
    __syncthreads();
    float tot = red[0] + red[1] + red[2] + red[3]
              + red[4] + red[5] + red[6] + red[7];
    float mu = tot * (1.0f / DH);
    __syncthreads();

    float d = val - mu;
    float s2 = d * d;
#pragma unroll
    for (int o = 16; o; o >>= 1) s2 += __shfl_xor_sync(0xffffffffu, s2, o);
    if (lane == 0) red[wrp] = s2;
    __syncthreads();
    float var = (red[0] + red[1] + red[2] + red[3]
               + red[4] + red[5] + red[6] + red[7]) * (1.0f / DH);

    float y = d * rsqrtf(var + LN_EPS) * gam[ch] + bet[ch];
    float act = (y > 0.0f) ? y : expm1f(y);

    if (LAST) {
        out[(size_t)v * DH + ch] = act;
    } else {
        __nv_bfloat16 hi = __float2bfloat16(act);
        g_Ahi[(size_t)v * DH + ch] = hi;
        g_Alo[(size_t)v * DH + ch] = __float2bfloat16(act - __bfloat162float(hi));
    }
}

// ---------------------------------------------------------------------------
extern "C" void kernel_launch(void* const* d_in, const int* in_sizes, int n_in,
                              void* d_out, int out_size) {
    const float* x   = (const float*)d_in[0];
    const float* Wt0 = (const float*)d_in[1];
    const float* bt0 = (const float*)d_in[2];
    const float* Wp0 = (const float*)d_in[3];
    const float* bp0 = (const float*)d_in[4];
    const float* g0  = (const float*)d_in[5];
    const float* b0  = (const float*)d_in[6];
    const float* Wt1 = (const float*)d_in[7];
    const float* bt1 = (const float*)d_in[8];
    const float* Wp1 = (const float*)d_in[9];
    const float* bp1 = (const float*)d_in[10];
    const float* g1  = (const float*)d_in[11];
    const float* b1  = (const float*)d_in[12];
    const float* Wt2 = (const float*)d_in[13];
    const float* bt2 = (const float*)d_in[14];
    const float* Wp2 = (const float*)d_in[15];
    const float* bp2 = (const float*)d_in[16];
    const float* g2  = (const float*)d_in[17];
    const float* b2  = (const float*)d_in[18];
    const int*   src = (const int*)d_in[19];
    const int*   dst = (const int*)d_in[20];
    float* out = (float*)d_out;

    // >48KB dynamic SMEM opt-in (runs immediately, not a captured node)
    cudaFuncSetAttribute(gemm_mma<DIN>, cudaFuncAttributeMaxDynamicSharedMemorySize, GEMM_SMEM);
    cudaFuncSetAttribute(gemm_mma<DH>,  cudaFuncAttributeMaxDynamicSharedMemorySize, GEMM_SMEM);

    // CSR build (dst adjacency, shared by all layers)
    zero_cnt_kernel<<<GN / 256, 256>>>();
    hist_kernel<<<EALL / 256, 256>>>(dst);
    scan_kernel<<<1, 1024>>>();
    fill_kernel<<<EALL / 256, 256>>>(src, dst);

    // Split input into bf16 hi/lo
    xconv_kernel<<<(GN * DIN) / 256, 256>>>(x);

    dim3 ggrid(GN / 128, 4);

    // Layer 0 (K = 128)
    wconv_kernel<DIN><<<(512 * DIN) / 256, 256>>>(Wt0, Wp0);
    gemm_mma<DIN><<<ggrid, 256, GEMM_SMEM>>>();
    fuse_kernel<false><<<GN, DH>>>(bt0, bp0, g0, b0, nullptr);

    // Layer 1 (K = 256)
    wconv_kernel<DH><<<(512 * DH) / 256, 256>>>(Wt1, Wp1);
    gemm_mma<DH><<<ggrid, 256, GEMM_SMEM>>>();
    fuse_kernel<false><<<GN, DH>>>(bt1, bp1, g1, b1, nullptr);

    // Layer 2 (K = 256), final output fp32
    wconv_kernel<DH><<<(512 * DH) / 256, 256>>>(Wt2, Wp2);
    gemm_mma<DH><<<ggrid, 256, GEMM_SMEM>>>();
    fuse_kernel<true><<<GN, DH>>>(bt2, bp2, g2, b2, out);
}

// round 6
// speedup vs baseline: 1.8457x; 1.1547x over previous
#include <cuda_runtime.h>
#include <cuda_bf16.h>
#include <cuda_fp16.h>
#include <cfloat>
#include <math.h>
#include <cstdint>

// Problem constants
#define GCNT 8
#define NNODE 2048
#define ETOT 34816              // 32768 random + 2048 self loops, per graph
#define EALL (GCNT * ETOT)      // 278528
#define GN (GCNT * NNODE)       // 16384
#define DIN 128
#define DH 256
#define LN_EPS 1e-5f

// ---------------------------------------------------------------------------
// Scratch (static device globals — allocation-free per harness rules)
// ---------------------------------------------------------------------------
__device__ float  g_T[GN * DH];
__device__ float  g_P[GN * DH];
__device__ __half g_Af[GN * DH];      // activations, single fp16
__device__ __half g_Bhi[512 * DH];    // concat(Wt,Wp) as [n=512][k=K], fp16 hi
__device__ __half g_Blo[512 * DH];    // fp16 residual
__device__ int g_rowptr[GN + 1];
__device__ int g_cnt[GN];
__device__ int g_col[EALL];

// ---------------------------------------------------------------------------
// CSR build (dst-sorted adjacency), reused across all 3 layers
// ---------------------------------------------------------------------------
__global__ void zero_cnt_kernel() {
    int i = blockIdx.x * blockDim.x + threadIdx.x;
    if (i < GN) g_cnt[i] = 0;
}

__global__ void hist_kernel(const int* __restrict__ dst) {
    int e = blockIdx.x * blockDim.x + threadIdx.x;
    if (e >= EALL) return;
    int g = e / ETOT;
    int d = dst[e] + g * NNODE;
    atomicAdd(&g_cnt[d], 1);
}

__global__ void scan_kernel() {
    __shared__ int sh[1024];
    int t = threadIdx.x;
    int base = t * 16;
    int local[16];
    int run = 0;
#pragma unroll
    for (int i = 0; i < 16; i++) { local[i] = run; run += g_cnt[base + i]; }
    sh[t] = run;
    __syncthreads();
    for (int d = 1; d < 1024; d <<= 1) {
        int v = (t >= d) ? sh[t - d] : 0;
        __syncthreads();
        sh[t] += v;
        __syncthreads();
    }
    int off = (t == 0) ? 0 : sh[t - 1];
#pragma unroll
    for (int i = 0; i < 16; i++) {
        g_rowptr[base + i] = off + local[i];
        g_cnt[base + i] = 0;
    }
    if (t == 1023) g_rowptr[GN] = sh[1023];
}

__global__ void fill_kernel(const int* __restrict__ src, const int* __restrict__ dst) {
    int e = blockIdx.x * blockDim.x + threadIdx.x;
    if (e >= EALL) return;
    int g = e / ETOT;
    int d = dst[e] + g * NNODE;
    int s = src[e] + g * NNODE;
    int pos = g_rowptr[d] + atomicAdd(&g_cnt[d], 1);
    g_col[pos] = s;
}

// ---------------------------------------------------------------------------
// Conversions
// ---------------------------------------------------------------------------
__global__ void xconv_kernel(const float* __restrict__ x) {
    int i = blockIdx.x * blockDim.x + threadIdx.x;   // over GN*DIN
    g_Af[i] = __float2half(x[i]);
}

template <int K>
__global__ void wconv_kernel(const float* __restrict__ Wt, const float* __restrict__ Wp) {
    int idx = blockIdx.x * blockDim.x + threadIdx.x;  // over 512*K
    if (idx >= 512 * K) return;
    int n = idx / K;
    int k = idx - n * K;
    float v = (n < 256) ? Wt[k * 256 + n] : Wp[k * 256 + (n - 256)];
    __half hi = __float2half(v);
    g_Bhi[idx] = hi;
    g_Blo[idx] = __float2half(v - __half2float(hi));
}

// ---------------------------------------------------------------------------
// mma.sync helpers (sm_80+ path — works on plain compute_100 target)
// ---------------------------------------------------------------------------
static __device__ __forceinline__ uint32_t s2u(const void* p) {
    uint32_t a;
    asm("{ .reg .u64 t; cvta.to.shared.u64 t, %1; cvt.u32.u64 %0, t; }"
        : "=r"(a) : "l"(p));
    return a;
}

static __device__ __forceinline__ void ldm_x4(uint32_t* r, uint32_t saddr) {
    asm volatile("ldmatrix.sync.aligned.m8n8.x4.shared.b16 {%0,%1,%2,%3}, [%4];"
        : "=r"(r[0]), "=r"(r[1]), "=r"(r[2]), "=r"(r[3]) : "r"(saddr));
}

static __device__ __forceinline__ void mma16816(float* c, const uint32_t* a,
                                                const uint32_t* b) {
    asm volatile(
        "mma.sync.aligned.m16n8k16.row.col.f32.f16.f16.f32 "
        "{%0,%1,%2,%3}, {%4,%5,%6,%7}, {%8,%9}, {%0,%1,%2,%3};"
        : "+f"(c[0]), "+f"(c[1]), "+f"(c[2]), "+f"(c[3])
        : "r"(a[0]), "r"(a[1]), "r"(a[2]), "r"(a[3]), "r"(b[0]), "r"(b[1]));
}

static __device__ __forceinline__ void cp16(uint32_t s, const void* g) {
    asm volatile("cp.async.cg.shared.global [%0], [%1], 16;" :: "r"(s), "l"(g));
}
#define CP_COMMIT() asm volatile("cp.async.commit_group;" ::: "memory")
#define CP_WAIT(N)  asm volatile("cp.async.wait_group %0;" :: "n"(N) : "memory")

// ---------------------------------------------------------------------------
// Tensor-core GEMM (2-term fp16): C[GN, 512] = A[GN, K] @ (Bh + Bl)[512, K]^T
//   C cols [0,256) -> g_T, [256,512) -> g_P
// grid = (GN/128, 4), 256 threads, 2 CTAs/SM. CTA tile 128x128, warp 64x32.
// 2-stage cp.async pipeline; 3 SMEM tiles (A, Bh, Bl), stride 40 halves.
// ---------------------------------------------------------------------------
#define ASTR 40
#define TILEB (128 * ASTR * 2)          // 10240 B per tile
#define STAGEB (3 * TILEB)              // A, Bh, Bl
#define GEMM_SMEM (2 * STAGEB)          // 61440 B

template <int K>
__global__ __launch_bounds__(256, 2)
void gemm_mma() {
    extern __shared__ __align__(16) char dsm[];
    const uint32_t sbase = s2u(dsm);

    const int tid  = threadIdx.x;
    const int wid  = tid >> 5;
    const int lane = tid & 31;
    const int wm = wid >> 2;          // 0..1
    const int wn = wid & 3;           // 0..3
    const int row0 = blockIdx.x * 128;
    const int by   = blockIdx.y;      // 0..3  -> C cols [by*128, by*128+128)
    const int n0   = by * 128;

    float acc[4][4][4] = {};

    // Staging geometry (per thread: 2 row-halves x 3 tiles x 16B)
    const int r0s = tid >> 2;                 // rows 0..63
    const int q0s = tid & 3;
    const uint32_t soff0 = (uint32_t)((r0s * ASTR + q0s * 8) * 2);
    const uint32_t soff1 = (uint32_t)(((r0s + 64) * ASTR + q0s * 8) * 2);

    // ldmatrix per-thread base byte offsets (validated mapping)
    const uint32_t aOffB = (uint32_t)(((wm * 64 + (lane & 15)) * ASTR
                                       + ((lane >> 4) << 3)) * 2);
    const uint32_t bOffB = (uint32_t)(((wn * 32 + ((lane >> 4) << 3) + (lane & 7)) * ASTR
                                       + (((lane >> 3) & 1) << 3)) * 2);

    constexpr int NCH = K / 32;

    auto issue = [&](int c, int stage) {
        const int k0 = c * 32;
        const uint32_t sb = sbase + stage * STAGEB;
        {
            size_t ga = (size_t)(row0 + r0s) * K + k0 + q0s * 8;
            size_t gb = (size_t)(n0 + r0s) * K + k0 + q0s * 8;
            cp16(sb + 0 * TILEB + soff0, g_Af  + ga);
            cp16(sb + 1 * TILEB + soff0, g_Bhi + gb);
            cp16(sb + 2 * TILEB + soff0, g_Blo + gb);
        }
        {
            size_t ga = (size_t)(row0 + 64 + r0s) * K + k0 + q0s * 8;
            size_t gb = (size_t)(n0 + 64 + r0s) * K + k0 + q0s * 8;
            cp16(sb + 0 * TILEB + soff1, g_Af  + ga);
            cp16(sb + 1 * TILEB + soff1, g_Bhi + gb);
            cp16(sb + 2 * TILEB + soff1, g_Blo + gb);
        }
        CP_COMMIT();
    };

    issue(0, 0);

    for (int c = 0; c < NCH; c++) {
        const int cur = c & 1;
        if (c + 1 < NCH) {
            issue(c + 1, cur ^ 1);
            CP_WAIT(1);
        } else {
            CP_WAIT(0);
        }
        __syncthreads();

        const uint32_t sb = sbase + cur * STAGEB;
        const uint32_t aA = sb + 0 * TILEB + aOffB;
        const uint32_t bH = sb + 1 * TILEB + bOffB;
        const uint32_t bL = sb + 2 * TILEB + bOffB;

#pragma unroll
        for (int s = 0; s < 2; s++) {
            const uint32_t sk = (uint32_t)(s * 32);   // +16 k-elems = 32 bytes
            uint32_t ah[4][4], bh[2][4], bl[2][4];
#pragma unroll
            for (int mt = 0; mt < 4; mt++)
                ldm_x4(ah[mt], aA + mt * (16 * ASTR * 2) + sk);
#pragma unroll
            for (int p = 0; p < 2; p++) {
                ldm_x4(bh[p], bH + p * (16 * ASTR * 2) + sk);
                ldm_x4(bl[p], bL + p * (16 * ASTR * 2) + sk);
            }
#pragma unroll
            for (int mt = 0; mt < 4; mt++)
#pragma unroll
                for (int nt = 0; nt < 4; nt++) {
                    const uint32_t* Bh = &bh[nt >> 1][(nt & 1) * 2];
                    const uint32_t* Bl = &bl[nt >> 1][(nt & 1) * 2];
                    mma16816(acc[mt][nt], ah[mt], Bh);
                    mma16816(acc[mt][nt], ah[mt], Bl);
                }
        }
        __syncthreads();
    }

    // Epilogue: cols [0,256) of C -> g_T, [256,512) -> g_P
    float* __restrict__ outp = (by < 2) ? g_T : g_P;
    const int col0 = (by & 1) * 128 + wn * 32;
    const int g  = lane >> 2;
    const int tg = lane & 3;
#pragma unroll
    for (int mt = 0; mt < 4; mt++) {
        int r = row0 + wm * 64 + mt * 16 + g;
#pragma unroll
        for (int nt = 0; nt < 4; nt++) {
            int cc = col0 + nt * 8 + tg * 2;
            *(float2*)&outp[(size_t)r * DH + cc] =
                make_float2(acc[mt][nt][0], acc[mt][nt][1]);
            *(float2*)&outp[(size_t)(r + 8) * DH + cc] =
                make_float2(acc[mt][nt][2], acc[mt][nt][3]);
        }
    }
}

// ---------------------------------------------------------------------------
// Fused per-node: gather-min over src neighbors + combine + LayerNorm + ELU
// grid = GN blocks, block = 256 threads (one per channel).
// LAST: write fp32 to out;  else: write fp16 into g_Af.
// ---------------------------------------------------------------------------
template <bool LAST>
__global__ __launch_bounds__(DH)
void fuse_kernel(const float* __restrict__ bt, const float* __restrict__ bp,
                 const float* __restrict__ gam, const float* __restrict__ bet,
                 float* __restrict__ out) {
    const int v = blockIdx.x;
    const int ch = threadIdx.x;
    const int beg = g_rowptr[v];
    const int end = g_rowptr[v + 1];

    float m0 = FLT_MAX, m1 = FLT_MAX, m2 = FLT_MAX, m3 = FLT_MAX;
    int e = beg;
    for (; e + 4 <= end; e += 4) {
        int s0 = g_col[e + 0];
        int s1 = g_col[e + 1];
        int s2 = g_col[e + 2];
        int s3 = g_col[e + 3];
        m0 = fminf(m0, g_T[(size_t)s0 * DH + ch]);
        m1 = fminf(m1, g_T[(size_t)s1 * DH + ch]);
        m2 = fminf(m2, g_T[(size_t)s2 * DH + ch]);
        m3 = fminf(m3, g_T[(size_t)s3 * DH + ch]);
    }
    for (; e < end; e++) m0 = fminf(m0, g_T[(size_t)g_col[e] * DH + ch]);
    float mn = fminf(fminf(m0, m1), fminf(m2, m3));

    float val = g_T[(size_t)v * DH + ch] + g_P[(size_t)v * DH + ch]
              + bt[ch] + bp[ch] - mn;

    __shared__ float red[8];
    const int lane = threadIdx.x & 31;
    const int wrp  = threadIdx.x >> 5;

    float s = val;
#pragma unroll
    for (int o = 16; o; o >>= 1) s += __shfl_xor_sync(0xffffffffu, s, o);
    if (lane == 0) red[wrp] = s;
    __syncthreads();
    float tot = red[0] + red[1] + red[2] + red[3]
              + red[4] + red[5] + red[6] + red[7];
    float mu = tot * (1.0f / DH);
    __syncthreads();

    float d = val - mu;
    float s2 = d * d;
#pragma unroll
    for (int o = 16; o; o >>= 1) s2 += __shfl_xor_sync(0xffffffffu, s2, o);
    if (lane == 0) red[wrp] = s2;
    __syncthreads();
    float var = (red[0] + red[1] + red[2] + red[3]
               + red[4] + red[5] + red[6] + red[7]) * (1.0f / DH);

    float y = d * rsqrtf(var + LN_EPS) * gam[ch] + bet[ch];
    float act = (y > 0.0f) ? y : expm1f(y);

    if (LAST) {
        out[(size_t)v * DH + ch] = act;
    } else {
        g_Af[(size_t)v * DH + ch] = __float2half(act);
    }
}

// ---------------------------------------------------------------------------
extern "C" void kernel_launch(void* const* d_in, const int* in_sizes, int n_in,
                              void* d_out, int out_size) {
    const float* x   = (const float*)d_in[0];
    const float* Wt0 = (const float*)d_in[1];
    const float* bt0 = (const float*)d_in[2];
    const float* Wp0 = (const float*)d_in[3];
    const float* bp0 = (const float*)d_in[4];
    const float* g0  = (const float*)d_in[5];
    const float* b0  = (const float*)d_in[6];
    const float* Wt1 = (const float*)d_in[7];
    const float* bt1 = (const float*)d_in[8];
    const float* Wp1 = (const float*)d_in[9];
    const float* bp1 = (const float*)d_in[10];
    const float* g1  = (const float*)d_in[11];
    const float* b1  = (const float*)d_in[12];
    const float* Wt2 = (const float*)d_in[13];
    const float* bt2 = (const float*)d_in[14];
    const float* Wp2 = (const float*)d_in[15];
    const float* bp2 = (const float*)d_in[16];
    const float* g2  = (const float*)d_in[17];
    const float* b2  = (const float*)d_in[18];
    const int*   src = (const int*)d_in[19];
    const int*   dst = (const int*)d_in[20];
    float* out = (float*)d_out;

    // >48KB dynamic SMEM opt-in (runs immediately, not a captured node)
    cudaFuncSetAttribute(gemm_mma<DIN>, cudaFuncAttributeMaxDynamicSharedMemorySize, GEMM_SMEM);
    cudaFuncSetAttribute(gemm_mma<DH>,  cudaFuncAttributeMaxDynamicSharedMemorySize, GEMM_SMEM);

    // CSR build (dst adjacency, shared by all layers)
    zero_cnt_kernel<<<GN / 256, 256>>>();
    hist_kernel<<<EALL / 256, 256>>>(dst);
    scan_kernel<<<1, 1024>>>();
    fill_kernel<<<EALL / 256, 256>>>(src, dst);

    // Convert input to fp16
    xconv_kernel<<<(GN * DIN) / 256, 256>>>(x);

    dim3 ggrid(GN / 128, 4);

    // Layer 0 (K = 128)
    wconv_kernel<DIN><<<(512 * DIN) / 256, 256>>>(Wt0, Wp0);
    gemm_mma<DIN><<<ggrid, 256, GEMM_SMEM>>>();
    fuse_kernel<false><<<GN, DH>>>(bt0, bp0, g0, b0, nullptr);

    // Layer 1 (K = 256)
    wconv_kernel<DH><<<(512 * DH) / 256, 256>>>(Wt1, Wp1);
    gemm_mma<DH><<<ggrid, 256, GEMM_SMEM>>>();
    fuse_kernel<false><<<GN, DH>>>(bt1, bp1, g1, b1, nullptr);

    // Layer 2 (K = 256), final output fp32
    wconv_kernel<DH><<<(512 * DH) / 256, 256>>>(Wt2, Wp2);
    gemm_mma<DH><<<ggrid, 256, GEMM_SMEM>>>();
    fuse_kernel<true><<<GN, DH>>>(bt2, bp2, g2, b2, out);
}

// round 7
// speedup vs baseline: 1.9548x; 1.0591x over previous
#include <cuda_runtime.h>
#include <cuda_bf16.h>
#include <cuda_fp16.h>
#include <cfloat>
#include <math.h>
#include <cstdint>

// Problem constants
#define GCNT 8
#define NNODE 2048
#define ETOT 34816              // 32768 random + 2048 self loops, per graph
#define EALL (GCNT * ETOT)      // 278528
#define GN (GCNT * NNODE)       // 16384
#define DIN 128
#define DH 256
#define LN_EPS 1e-5f

#define WTOT (512 * (128 + 256 + 256))   // 327680 weight elems (all layers)
#define LOFF0 0
#define LOFF1 (512 * 128)
#define LOFF2 (512 * 128 + 512 * 256)

// ---------------------------------------------------------------------------
// Scratch (static device globals — allocation-free per harness rules)
// ---------------------------------------------------------------------------
__device__ float  g_T[GN * DH];
__device__ float  g_P[GN * DH];
__device__ __half g_Af[GN * DH];      // activations, single fp16
__device__ __half g_Bhi[WTOT];        // concat(Wt,Wp) [n=512][k=K], all 3 layers
__device__ __half g_Blo[WTOT];        // fp16 residual
__device__ int g_rowptr[GN + 1];
__device__ int g_cnt[GN];
__device__ int g_col[EALL];

// ---------------------------------------------------------------------------
// CSR build (dst-sorted adjacency), reused across all 3 layers
// ---------------------------------------------------------------------------
__global__ void hist_kernel(const int* __restrict__ dst) {
    int e = blockIdx.x * blockDim.x + threadIdx.x;
    if (e >= EALL) return;
    int g = e / ETOT;
    int d = dst[e] + g * NNODE;
    atomicAdd(&g_cnt[d], 1);
}

__global__ void scan_kernel() {
    __shared__ int sh[1024];
    int t = threadIdx.x;
    int base = t * 16;
    int local[16];
    int run = 0;
#pragma unroll
    for (int i = 0; i < 16; i++) { local[i] = run; run += g_cnt[base + i]; }
    sh[t] = run;
    __syncthreads();
    for (int d = 1; d < 1024; d <<= 1) {
        int v = (t >= d) ? sh[t - d] : 0;
        __syncthreads();
        sh[t] += v;
        __syncthreads();
    }
    int off = (t == 0) ? 0 : sh[t - 1];
#pragma unroll
    for (int i = 0; i < 16; i++) {
        g_rowptr[base + i] = off + local[i];
        g_cnt[base + i] = 0;
    }
    if (t == 1023) g_rowptr[GN] = sh[1023];
}

__global__ void fill_kernel(const int* __restrict__ src, const int* __restrict__ dst) {
    int e = blockIdx.x * blockDim.x + threadIdx.x;
    if (e >= EALL) return;
    int g = e / ETOT;
    int d = dst[e] + g * NNODE;
    int s = src[e] + g * NNODE;
    int pos = g_rowptr[d] + atomicAdd(&g_cnt[d], 1);
    g_col[pos] = s;
}

// ---------------------------------------------------------------------------
// prep: zero g_cnt, convert x -> fp16, convert all 3 layers' weights -> hi/lo
// grid covers GN*DIN + WTOT elements exactly.
// ---------------------------------------------------------------------------
__global__ void prep_kernel(const float* __restrict__ x,
                            const float* __restrict__ Wt0, const float* __restrict__ Wp0,
                            const float* __restrict__ Wt1, const float* __restrict__ Wp1,
                            const float* __restrict__ Wt2, const float* __restrict__ Wp2) {
    int idx = blockIdx.x * blockDim.x + threadIdx.x;
    if (idx < GN) g_cnt[idx] = 0;
    if (idx < GN * DIN) {
        g_Af[idx] = __float2half(x[idx]);
        return;
    }
    int wi = idx - GN * DIN;   // 0 .. WTOT-1
    const float *Wt, *Wp;
    int K, rel;
    if (wi < LOFF1) { Wt = Wt0; Wp = Wp0; K = 128; rel = wi; }
    else if (wi < LOFF2) { Wt = Wt1; Wp = Wp1; K = 256; rel = wi - LOFF1; }
    else { Wt = Wt2; Wp = Wp2; K = 256; rel = wi - LOFF2; }
    int n = rel / K;
    int k = rel - n * K;
    float v = (n < 256) ? Wt[k * 256 + n] : Wp[k * 256 + (n - 256)];
    __half hi = __float2half(v);
    g_Bhi[wi] = hi;
    g_Blo[wi] = __float2half(v - __half2float(hi));
}

// ---------------------------------------------------------------------------
// mma.sync helpers (sm_80+ path — works on plain compute_100 target)
// ---------------------------------------------------------------------------
static __device__ __forceinline__ uint32_t s2u(const void* p) {
    uint32_t a;
    asm("{ .reg .u64 t; cvta.to.shared.u64 t, %1; cvt.u32.u64 %0, t; }"
        : "=r"(a) : "l"(p));
    return a;
}

static __device__ __forceinline__ void ldm_x4(uint32_t* r, uint32_t saddr) {
    asm volatile("ldmatrix.sync.aligned.m8n8.x4.shared.b16 {%0,%1,%2,%3}, [%4];"
        : "=r"(r[0]), "=r"(r[1]), "=r"(r[2]), "=r"(r[3]) : "r"(saddr));
}

static __device__ __forceinline__ void mma16816(float* c, const uint32_t* a,
                                                const uint32_t* b) {
    asm volatile(
        "mma.sync.aligned.m16n8k16.row.col.f32.f16.f16.f32 "
        "{%0,%1,%2,%3}, {%4,%5,%6,%7}, {%8,%9}, {%0,%1,%2,%3};"
        : "+f"(c[0]), "+f"(c[1]), "+f"(c[2]), "+f"(c[3])
        : "r"(a[0]), "r"(a[1]), "r"(a[2]), "r"(a[3]), "r"(b[0]), "r"(b[1]));
}

static __device__ __forceinline__ void cp16(uint32_t s, const void* g) {
    asm volatile("cp.async.cg.shared.global [%0], [%1], 16;" :: "r"(s), "l"(g));
}
#define CP_COMMIT() asm volatile("cp.async.commit_group;" ::: "memory")
#define CP_WAIT(N)  asm volatile("cp.async.wait_group %0;" :: "n"(N) : "memory")

// ---------------------------------------------------------------------------
// Tensor-core GEMM (2-term fp16): C[GN, 512] = A[GN, K] @ (Bh + Bl)[512, K]^T
//   C cols [0,256) -> g_T, [256,512) -> g_P
// grid = (GN/128, 4), 256 threads, 2 CTAs/SM. CTA tile 128x128, warp 64x32.
// 3-stage cp.async pipeline, ONE barrier per chunk; Bh-sweep then Bl-sweep
// so no back-to-back RAW on accumulators.
// ---------------------------------------------------------------------------
#define ASTR 40
#define TILEB (128 * ASTR * 2)          // 10240 B per tile
#define STAGEB (3 * TILEB)              // A, Bh, Bl
#define NSTAGE 3
#define GEMM_SMEM (NSTAGE * STAGEB)     // 92160 B

template <int K>
__global__ __launch_bounds__(256, 2)
void gemm_mma(int loff) {
    extern __shared__ __align__(16) char dsm[];
    const uint32_t sbase = s2u(dsm);

    const int tid  = threadIdx.x;
    const int wid  = tid >> 5;
    const int lane = tid & 31;
    const int wm = wid >> 2;          // 0..1
    const int wn = wid & 3;           // 0..3
    const int row0 = blockIdx.x * 128;
    const int by   = blockIdx.y;      // 0..3  -> C cols [by*128, by*128+128)
    const int n0   = by * 128;

    const __half* __restrict__ Bh_g = g_Bhi + loff;
    const __half* __restrict__ Bl_g = g_Blo + loff;

    float acc[4][4][4] = {};

    // Staging geometry (per thread: 2 row-halves x 3 tiles x 16B)
    const int r0s = tid >> 2;                 // rows 0..63
    const int q0s = tid & 3;
    const uint32_t soff0 = (uint32_t)((r0s * ASTR + q0s * 8) * 2);
    const uint32_t soff1 = (uint32_t)(((r0s + 64) * ASTR + q0s * 8) * 2);

    // ldmatrix per-thread base byte offsets (validated mapping)
    const uint32_t aOffB = (uint32_t)(((wm * 64 + (lane & 15)) * ASTR
                                       + ((lane >> 4) << 3)) * 2);
    const uint32_t bOffB = (uint32_t)(((wn * 32 + ((lane >> 4) << 3) + (lane & 7)) * ASTR
                                       + (((lane >> 3) & 1) << 3)) * 2);

    constexpr int NCH = K / 32;

    auto issue = [&](int c, int stage) {
        const int k0 = c * 32;
        const uint32_t sb = sbase + stage * STAGEB;
        {
            size_t ga = (size_t)(row0 + r0s) * K + k0 + q0s * 8;
            size_t gb = (size_t)(n0 + r0s) * K + k0 + q0s * 8;
            cp16(sb + 0 * TILEB + soff0, g_Af + ga);
            cp16(sb + 1 * TILEB + soff0, Bh_g + gb);
            cp16(sb + 2 * TILEB + soff0, Bl_g + gb);
        }
        {
            size_t ga = (size_t)(row0 + 64 + r0s) * K + k0 + q0s * 8;
            size_t gb = (size_t)(n0 + 64 + r0s) * K + k0 + q0s * 8;
            cp16(sb + 0 * TILEB + soff1, g_Af + ga);
            cp16(sb + 1 * TILEB + soff1, Bh_g + gb);
            cp16(sb + 2 * TILEB + soff1, Bl_g + gb);
        }
        CP_COMMIT();
    };

    issue(0, 0);
    issue(1, 1);

    for (int c = 0; c < NCH; c++) {
        if (c + 1 < NCH) { CP_WAIT(1); } else { CP_WAIT(0); }
        __syncthreads();   // all warps done with stage (c+2)%NSTAGE from iter c-1

        if (c + 2 < NCH) issue(c + 2, (c + 2) % NSTAGE);

        const uint32_t sb = sbase + (c % NSTAGE) * STAGEB;
        const uint32_t aA = sb + 0 * TILEB + aOffB;
        const uint32_t bH = sb + 1 * TILEB + bOffB;
        const uint32_t bL = sb + 2 * TILEB + bOffB;

#pragma unroll
        for (int s = 0; s < 2; s++) {
            const uint32_t sk = (uint32_t)(s * 32);   // +16 k-elems = 32 bytes
            uint32_t ah[4][4], bh[2][4], bl[2][4];
#pragma unroll
            for (int mt = 0; mt < 4; mt++)
                ldm_x4(ah[mt], aA + mt * (16 * ASTR * 2) + sk);
#pragma unroll
            for (int p = 0; p < 2; p++) {
                ldm_x4(bh[p], bH + p * (16 * ASTR * 2) + sk);
                ldm_x4(bl[p], bL + p * (16 * ASTR * 2) + sk);
            }
            // Sweep all tiles with Bh, then all with Bl: 16 independent MMAs
            // between consecutive touches of any accumulator (no RAW stall).
#pragma unroll
            for (int mt = 0; mt < 4; mt++)
#pragma unroll
                for (int nt = 0; nt < 4; nt++)
                    mma16816(acc[mt][nt], ah[mt], &bh[nt >> 1][(nt & 1) * 2]);
#pragma unroll
            for (int mt = 0; mt < 4; mt++)
#pragma unroll
                for (int nt = 0; nt < 4; nt++)
                    mma16816(acc[mt][nt], ah[mt], &bl[nt >> 1][(nt & 1) * 2]);
        }
    }

    // Epilogue: cols [0,256) of C -> g_T, [256,512) -> g_P
    float* __restrict__ outp = (by < 2) ? g_T : g_P;
    const int col0 = (by & 1) * 128 + wn * 32;
    const int g  = lane >> 2;
    const int tg = lane & 3;
#pragma unroll
    for (int mt = 0; mt < 4; mt++) {
        int r = row0 + wm * 64 + mt * 16 + g;
#pragma unroll
        for (int nt = 0; nt < 4; nt++) {
            int cc = col0 + nt * 8 + tg * 2;
            *(float2*)&outp[(size_t)r * DH + cc] =
                make_float2(acc[mt][nt][0], acc[mt][nt][1]);
            *(float2*)&outp[(size_t)(r + 8) * DH + cc] =
                make_float2(acc[mt][nt][2], acc[mt][nt][3]);
        }
    }
}

// ---------------------------------------------------------------------------
// Fused per-node: gather-min over src neighbors + combine + LayerNorm + ELU
// grid = GN blocks, block = 256 threads (one per channel).
// LAST: write fp32 to out;  else: write fp16 into g_Af.
// ---------------------------------------------------------------------------
template <bool LAST>
__global__ __launch_bounds__(DH)
void fuse_kernel(const float* __restrict__ bt, const float* __restrict__ bp,
                 const float* __restrict__ gam, const float* __restrict__ bet,
                 float* __restrict__ out) {
    const int v = blockIdx.x;
    const int ch = threadIdx.x;
    const int beg = g_rowptr[v];
    const int end = g_rowptr[v + 1];

    float m0 = FLT_MAX, m1 = FLT_MAX, m2 = FLT_MAX, m3 = FLT_MAX;
    int e = beg;
    for (; e + 4 <= end; e += 4) {
        int s0 = g_col[e + 0];
        int s1 = g_col[e + 1];
        int s2 = g_col[e + 2];
        int s3 = g_col[e + 3];
        m0 = fminf(m0, g_T[(size_t)s0 * DH + ch]);
        m1 = fminf(m1, g_T[(size_t)s1 * DH + ch]);
        m2 = fminf(m2, g_T[(size_t)s2 * DH + ch]);
        m3 = fminf(m3, g_T[(size_t)s3 * DH + ch]);
    }
    for (; e < end; e++) m0 = fminf(m0, g_T[(size_t)g_col[e] * DH + ch]);
    float mn = fminf(fminf(m0, m1), fminf(m2, m3));

    float val = g_T[(size_t)v * DH + ch] + g_P[(size_t)v * DH + ch]
              + bt[ch] + bp[ch] - mn;

    __shared__ float red[8];
    const int lane = threadIdx.x & 31;
    const int wrp  = threadIdx.x >> 5;

    float s = val;
#pragma unroll
    for (int o = 16; o; o >>= 1) s += __shfl_xor_sync(0xffffffffu, s, o);
    if (lane == 0) red[wrp] = s;
    __syncthreads();
    float tot = red[0] + red[1] + red[2] + red[3]
              + red[4] + red[5] + red[6] + red[7];
    float mu = tot * (1.0f / DH);
    __syncthreads();

    float d = val - mu;
    float s2 = d * d;
#pragma unroll
    for (int o = 16; o; o >>= 1) s2 += __shfl_xor_sync(0xffffffffu, s2, o);
    if (lane == 0) red[wrp] = s2;
    __syncthreads();
    float var = (red[0] + red[1] + red[2] + red[3]
               + red[4] + red[5] + red[6] + red[7]) * (1.0f / DH);

    float y = d * rsqrtf(var + LN_EPS) * gam[ch] + bet[ch];
    float act = (y > 0.0f) ? y : expm1f(y);

    if (LAST) {
        out[(size_t)v * DH + ch] = act;
    } else {
        g_Af[(size_t)v * DH + ch] = __float2half(act);
    }
}

// ---------------------------------------------------------------------------
extern "C" void kernel_launch(void* const* d_in, const int* in_sizes, int n_in,
                              void* d_out, int out_size) {
    const float* x   = (const float*)d_in[0];
    const float* Wt0 = (const float*)d_in[1];
    const float* bt0 = (const float*)d_in[2];
    const float* Wp0 = (const float*)d_in[3];
    const float* bp0 = (const float*)d_in[4];
    const float* g0  = (const float*)d_in[5];
    const float* b0  = (const float*)d_in[6];
    const float* Wt1 = (const float*)d_in[7];
    const float* bt1 = (const float*)d_in[8];
    const float* Wp1 = (const float*)d_in[9];
    const float* bp1 = (const float*)d_in[10];
    const float* g1  = (const float*)d_in[11];
    const float* b1  = (const float*)d_in[12];
    const float* Wt2 = (const float*)d_in[13];
    const float* bt2 = (const float*)d_in[14];
    const float* Wp2 = (const float*)d_in[15];
    const float* bp2 = (const float*)d_in[16];
    const float* g2  = (const float*)d_in[17];
    const float* b2  = (const float*)d_in[18];
    const int*   src = (const int*)d_in[19];
    const int*   dst = (const int*)d_in[20];
    float* out = (float*)d_out;

    // >48KB dynamic SMEM opt-in (runs immediately, not a captured node)
    cudaFuncSetAttribute(gemm_mma<DIN>, cudaFuncAttributeMaxDynamicSharedMemorySize, GEMM_SMEM);
    cudaFuncSetAttribute(gemm_mma<DH>,  cudaFuncAttributeMaxDynamicSharedMemorySize, GEMM_SMEM);

    // prep (zero cnt + all conversions) runs first; CSR build follows
    prep_kernel<<<(GN * DIN + WTOT) / 256, 256>>>(x, Wt0, Wp0, Wt1, Wp1, Wt2, Wp2);
    hist_kernel<<<EALL / 256, 256>>>(dst);
    scan_kernel<<<1, 1024>>>();
    fill_kernel<<<EALL / 256, 256>>>(src, dst);

    dim3 ggrid(GN / 128, 4);

    // Layer 0 (K = 128)
    gemm_mma<DIN><<<ggrid, 256, GEMM_SMEM>>>(LOFF0);
    fuse_kernel<false><<<GN, DH>>>(bt0, bp0, g0, b0, nullptr);

    // Layer 1 (K = 256)
    gemm_mma<DH><<<ggrid, 256, GEMM_SMEM>>>(LOFF1);
    fuse_kernel<false><<<GN, DH>>>(bt1, bp1, g1, b1, nullptr);

    // Layer 2 (K = 256), final output fp32
    gemm_mma<DH><<<ggrid, 256, GEMM_SMEM>>>(LOFF2);
    fuse_kernel<true><<<GN, DH>>>(bt2, bp2, g2, b2, out);
}

// round 8
// speedup vs baseline: 2.4046x; 1.2301x over previous
#include <cuda_runtime.h>
#include <cuda_bf16.h>
#include <cuda_fp16.h>
#include <cfloat>
#include <math.h>
#include <cstdint>

// Problem constants
#define GCNT 8
#define NNODE 2048
#define ETOT 34816              // 32768 random + 2048 self loops, per graph
#define EALL (GCNT * ETOT)      // 278528
#define GN (GCNT * NNODE)       // 16384
#define DIN 128
#define DH 256
#define LN_EPS 1e-5f

#define WTOT (512 * (128 + 256 + 256))   // 327680 weight elems (all layers)
#define LOFF0 0
#define LOFF1 (512 * 128)
#define LOFF2 (512 * 128 + 512 * 256)

// ---------------------------------------------------------------------------
// Scratch (static device globals — allocation-free per harness rules)
// ---------------------------------------------------------------------------
__device__ float  g_T[GN * DH];
__device__ float  g_P[GN * DH];
__device__ __half g_T16[GN * DH];     // fp16 shadow of T for the gather-min
__device__ __half g_Af[GN * DH];      // activations, single fp16
__device__ __half g_Bhi[WTOT];        // concat(Wt,Wp) [n=512][k=K], all 3 layers
__device__ __half g_Blo[WTOT];        // fp16 residual
__device__ int g_rowptr[GN + 1];
__device__ int g_cnt[GN];
__device__ int g_col[EALL];

// ---------------------------------------------------------------------------
// CSR build (dst-sorted adjacency), reused across all 3 layers
// ---------------------------------------------------------------------------
__global__ void hist_kernel(const int* __restrict__ dst) {
    int e = blockIdx.x * blockDim.x + threadIdx.x;
    if (e >= EALL) return;
    int g = e / ETOT;
    int d = dst[e] + g * NNODE;
    atomicAdd(&g_cnt[d], 1);
}

__global__ void scan_kernel() {
    __shared__ int sh[1024];
    int t = threadIdx.x;
    int base = t * 16;
    int local[16];
    int run = 0;
#pragma unroll
    for (int i = 0; i < 16; i++) { local[i] = run; run += g_cnt[base + i]; }
    sh[t] = run;
    __syncthreads();
    for (int d = 1; d < 1024; d <<= 1) {
        int v = (t >= d) ? sh[t - d] : 0;
        __syncthreads();
        sh[t] += v;
        __syncthreads();
    }
    int off = (t == 0) ? 0 : sh[t - 1];
#pragma unroll
    for (int i = 0; i < 16; i++) {
        g_rowptr[base + i] = off + local[i];
        g_cnt[base + i] = 0;
    }
    if (t == 1023) g_rowptr[GN] = sh[1023];
}

__global__ void fill_kernel(const int* __restrict__ src, const int* __restrict__ dst) {
    int e = blockIdx.x * blockDim.x + threadIdx.x;
    if (e >= EALL) return;
    int g = e / ETOT;
    int d = dst[e] + g * NNODE;
    int s = src[e] + g * NNODE;
    int pos = g_rowptr[d] + atomicAdd(&g_cnt[d], 1);
    g_col[pos] = s;
}

// ---------------------------------------------------------------------------
// prep: zero g_cnt, convert x -> fp16, convert all 3 layers' weights -> hi/lo
// ---------------------------------------------------------------------------
__global__ void prep_kernel(const float* __restrict__ x,
                            const float* __restrict__ Wt0, const float* __restrict__ Wp0,
                            const float* __restrict__ Wt1, const float* __restrict__ Wp1,
                            const float* __restrict__ Wt2, const float* __restrict__ Wp2) {
    int idx = blockIdx.x * blockDim.x + threadIdx.x;
    if (idx < GN) g_cnt[idx] = 0;
    if (idx < GN * DIN) {
        g_Af[idx] = __float2half(x[idx]);
        return;
    }
    int wi = idx - GN * DIN;   // 0 .. WTOT-1
    const float *Wt, *Wp;
    int K, rel;
    if (wi < LOFF1) { Wt = Wt0; Wp = Wp0; K = 128; rel = wi; }
    else if (wi < LOFF2) { Wt = Wt1; Wp = Wp1; K = 256; rel = wi - LOFF1; }
    else { Wt = Wt2; Wp = Wp2; K = 256; rel = wi - LOFF2; }
    int n = rel / K;
    int k = rel - n * K;
    float v = (n < 256) ? Wt[k * 256 + n] : Wp[k * 256 + (n - 256)];
    __half hi = __float2half(v);
    g_Bhi[wi] = hi;
    g_Blo[wi] = __float2half(v - __half2float(hi));
}

// ---------------------------------------------------------------------------
// mma.sync helpers (sm_80+ path — works on plain compute_100 target)
// ---------------------------------------------------------------------------
static __device__ __forceinline__ uint32_t s2u(const void* p) {
    uint32_t a;
    asm("{ .reg .u64 t; cvta.to.shared.u64 t, %1; cvt.u32.u64 %0, t; }"
        : "=r"(a) : "l"(p));
    return a;
}

static __device__ __forceinline__ void ldm_x4(uint32_t* r, uint32_t saddr) {
    asm volatile("ldmatrix.sync.aligned.m8n8.x4.shared.b16 {%0,%1,%2,%3}, [%4];"
        : "=r"(r[0]), "=r"(r[1]), "=r"(r[2]), "=r"(r[3]) : "r"(saddr));
}

static __device__ __forceinline__ void mma16816(float* c, const uint32_t* a,
                                                const uint32_t* b) {
    asm volatile(
        "mma.sync.aligned.m16n8k16.row.col.f32.f16.f16.f32 "
        "{%0,%1,%2,%3}, {%4,%5,%6,%7}, {%8,%9}, {%0,%1,%2,%3};"
        : "+f"(c[0]), "+f"(c[1]), "+f"(c[2]), "+f"(c[3])
        : "r"(a[0]), "r"(a[1]), "r"(a[2]), "r"(a[3]), "r"(b[0]), "r"(b[1]));
}

static __device__ __forceinline__ void cp16(uint32_t s, const void* g) {
    asm volatile("cp.async.cg.shared.global [%0], [%1], 16;" :: "r"(s), "l"(g));
}
#define CP_COMMIT() asm volatile("cp.async.commit_group;" ::: "memory")
#define CP_WAIT(N)  asm volatile("cp.async.wait_group %0;" :: "n"(N) : "memory")

// ---------------------------------------------------------------------------
// Tensor-core GEMM (2-term fp16): C[GN, 512] = A[GN, K] @ (Bh + Bl)[512, K]^T
//   C cols [0,256) -> g_T (+ fp16 shadow g_T16), [256,512) -> g_P
// grid = (GN/128, 4), 256 threads, 2 CTAs/SM. CTA tile 128x128, warp 64x32.
// 3-stage cp.async pipeline, one barrier per chunk; Bh-sweep then Bl-sweep.
// ---------------------------------------------------------------------------
#define ASTR 40
#define TILEB (128 * ASTR * 2)          // 10240 B per tile
#define STAGEB (3 * TILEB)              // A, Bh, Bl
#define NSTAGE 3
#define GEMM_SMEM (NSTAGE * STAGEB)     // 92160 B

template <int K>
__global__ __launch_bounds__(256, 2)
void gemm_mma(int loff) {
    extern __shared__ __align__(16) char dsm[];
    const uint32_t sbase = s2u(dsm);

    const int tid  = threadIdx.x;
    const int wid  = tid >> 5;
    const int lane = tid & 31;
    const int wm = wid >> 2;          // 0..1
    const int wn = wid & 3;           // 0..3
    const int row0 = blockIdx.x * 128;
    const int by   = blockIdx.y;      // 0..3  -> C cols [by*128, by*128+128)
    const int n0   = by * 128;

    const __half* __restrict__ Bh_g = g_Bhi + loff;
    const __half* __restrict__ Bl_g = g_Blo + loff;

    float acc[4][4][4] = {};

    // Staging geometry (per thread: 2 row-halves x 3 tiles x 16B)
    const int r0s = tid >> 2;                 // rows 0..63
    const int q0s = tid & 3;
    const uint32_t soff0 = (uint32_t)((r0s * ASTR + q0s * 8) * 2);
    const uint32_t soff1 = (uint32_t)(((r0s + 64) * ASTR + q0s * 8) * 2);

    // ldmatrix per-thread base byte offsets (validated mapping)
    const uint32_t aOffB = (uint32_t)(((wm * 64 + (lane & 15)) * ASTR
                                       + ((lane >> 4) << 3)) * 2);
    const uint32_t bOffB = (uint32_t)(((wn * 32 + ((lane >> 4) << 3) + (lane & 7)) * ASTR
                                       + (((lane >> 3) & 1) << 3)) * 2);

    constexpr int NCH = K / 32;

    auto issue = [&](int c, int stage) {
        const int k0 = c * 32;
        const uint32_t sb = sbase + stage * STAGEB;
        {
            size_t ga = (size_t)(row0 + r0s) * K + k0 + q0s * 8;
            size_t gb = (size_t)(n0 + r0s) * K + k0 + q0s * 8;
            cp16(sb + 0 * TILEB + soff0, g_Af + ga);
            cp16(sb + 1 * TILEB + soff0, Bh_g + gb);
            cp16(sb + 2 * TILEB + soff0, Bl_g + gb);
        }
        {
            size_t ga = (size_t)(row0 + 64 + r0s) * K + k0 + q0s * 8;
            size_t gb = (size_t)(n0 + 64 + r0s) * K + k0 + q0s * 8;
            cp16(sb + 0 * TILEB + soff1, g_Af + ga);
            cp16(sb + 1 * TILEB + soff1, Bh_g + gb);
            cp16(sb + 2 * TILEB + soff1, Bl_g + gb);
        }
        CP_COMMIT();
    };

    issue(0, 0);
    issue(1, 1);

    for (int c = 0; c < NCH; c++) {
        if (c + 1 < NCH) { CP_WAIT(1); } else { CP_WAIT(0); }
        __syncthreads();

        if (c + 2 < NCH) issue(c + 2, (c + 2) % NSTAGE);

        const uint32_t sb = sbase + (c % NSTAGE) * STAGEB;
        const uint32_t aA = sb + 0 * TILEB + aOffB;
        const uint32_t bH = sb + 1 * TILEB + bOffB;
        const uint32_t bL = sb + 2 * TILEB + bOffB;

#pragma unroll
        for (int s = 0; s < 2; s++) {
            const uint32_t sk = (uint32_t)(s * 32);   // +16 k-elems = 32 bytes
            uint32_t ah[4][4], bh[2][4], bl[2][4];
#pragma unroll
            for (int mt = 0; mt < 4; mt++)
                ldm_x4(ah[mt], aA + mt * (16 * ASTR * 2) + sk);
#pragma unroll
            for (int p = 0; p < 2; p++) {
                ldm_x4(bh[p], bH + p * (16 * ASTR * 2) + sk);
                ldm_x4(bl[p], bL + p * (16 * ASTR * 2) + sk);
            }
            // Bh sweep then Bl sweep: no back-to-back RAW on any accumulator.
#pragma unroll
            for (int mt = 0; mt < 4; mt++)
#pragma unroll
                for (int nt = 0; nt < 4; nt++)
                    mma16816(acc[mt][nt], ah[mt], &bh[nt >> 1][(nt & 1) * 2]);
#pragma unroll
            for (int mt = 0; mt < 4; mt++)
#pragma unroll
                for (int nt = 0; nt < 4; nt++)
                    mma16816(acc[mt][nt], ah[mt], &bl[nt >> 1][(nt & 1) * 2]);
        }
    }

    // Epilogue
    const bool isT = (by < 2);
    float* __restrict__ outp = isT ? g_T : g_P;
    const int col0 = (by & 1) * 128 + wn * 32;
    const int g  = lane >> 2;
    const int tg = lane & 3;
#pragma unroll
    for (int mt = 0; mt < 4; mt++) {
        int r = row0 + wm * 64 + mt * 16 + g;
#pragma unroll
        for (int nt = 0; nt < 4; nt++) {
            int cc = col0 + nt * 8 + tg * 2;
            size_t i0 = (size_t)r * DH + cc;
            size_t i1 = (size_t)(r + 8) * DH + cc;
            *(float2*)&outp[i0] = make_float2(acc[mt][nt][0], acc[mt][nt][1]);
            *(float2*)&outp[i1] = make_float2(acc[mt][nt][2], acc[mt][nt][3]);
            if (isT) {
                *(__half2*)&g_T16[i0] =
                    __floats2half2_rn(acc[mt][nt][0], acc[mt][nt][1]);
                *(__half2*)&g_T16[i1] =
                    __floats2half2_rn(acc[mt][nt][2], acc[mt][nt][3]);
            }
        }
    }
}

// ---------------------------------------------------------------------------
// Fused per-node: gather-min (fp16 shadow) + combine + LayerNorm + ELU
// grid = GN blocks, 128 threads, 2 channels/thread (half2 gather loads).
// LAST: write fp32 to out;  else: write fp16 (half2) into g_Af.
// ---------------------------------------------------------------------------
template <bool LAST>
__global__ __launch_bounds__(128)
void fuse_kernel(const float* __restrict__ bt, const float* __restrict__ bp,
                 const float* __restrict__ gam, const float* __restrict__ bet,
                 float* __restrict__ out) {
    const int v = blockIdx.x;
    const int t = threadIdx.x;          // 0..127 -> channels 2t, 2t+1
    const int beg = g_rowptr[v];
    const int end = g_rowptr[v + 1];
    const __half2* __restrict__ T16 = (const __half2*)g_T16;

    float a0 = FLT_MAX, a1 = FLT_MAX, b0 = FLT_MAX, b1 = FLT_MAX;
    float c0 = FLT_MAX, c1 = FLT_MAX, d0 = FLT_MAX, d1 = FLT_MAX;
    int e = beg;
    for (; e + 4 <= end; e += 4) {
        int s0 = g_col[e + 0];
        int s1 = g_col[e + 1];
        int s2 = g_col[e + 2];
        int s3 = g_col[e + 3];
        __half2 h0 = T16[(size_t)s0 * 128 + t];
        __half2 h1 = T16[(size_t)s1 * 128 + t];
        __half2 h2 = T16[(size_t)s2 * 128 + t];
        __half2 h3 = T16[(size_t)s3 * 128 + t];
        a0 = fminf(a0, __low2float(h0));  a1 = fminf(a1, __high2float(h0));
        b0 = fminf(b0, __low2float(h1));  b1 = fminf(b1, __high2float(h1));
        c0 = fminf(c0, __low2float(h2));  c1 = fminf(c1, __high2float(h2));
        d0 = fminf(d0, __low2float(h3));  d1 = fminf(d1, __high2float(h3));
    }
    for (; e < end; e++) {
        __half2 h = T16[(size_t)g_col[e] * 128 + t];
        a0 = fminf(a0, __low2float(h));
        a1 = fminf(a1, __high2float(h));
    }
    float mn0 = fminf(fminf(a0, b0), fminf(c0, d0));
    float mn1 = fminf(fminf(a1, b1), fminf(c1, d1));

    size_t base2 = (size_t)v * 128 + t;
    float2 Tv = ((const float2*)g_T)[base2];
    float2 Pv = ((const float2*)g_P)[base2];
    float2 bT = ((const float2*)bt)[t];
    float2 bP = ((const float2*)bp)[t];
    float val0 = Tv.x + Pv.x + bT.x + bP.x - mn0;
    float val1 = Tv.y + Pv.y + bT.y + bP.y - mn1;

    // LayerNorm over 256 channels (2 per thread, 4 warps)
    __shared__ float red[4];
    const int lane = t & 31;
    const int wrp  = t >> 5;

    float s = val0 + val1;
#pragma unroll
    for (int o = 16; o; o >>= 1) s += __shfl_xor_sync(0xffffffffu, s, o);
    if (lane == 0) red[wrp] = s;
    __syncthreads();
    float mu = (red[0] + red[1] + red[2] + red[3]) * (1.0f / DH);
    __syncthreads();

    float e0 = val0 - mu, e1 = val1 - mu;
    float s2 = e0 * e0 + e1 * e1;
#pragma unroll
    for (int o = 16; o; o >>= 1) s2 += __shfl_xor_sync(0xffffffffu, s2, o);
    if (lane == 0) red[wrp] = s2;
    __syncthreads();
    float var = (red[0] + red[1] + red[2] + red[3]) * (1.0f / DH);
    float rs = rsqrtf(var + LN_EPS);

    float2 gm = ((const float2*)gam)[t];
    float2 bb = ((const float2*)bet)[t];
    float y0 = e0 * rs * gm.x + bb.x;
    float y1 = e1 * rs * gm.y + bb.y;
    float act0 = (y0 > 0.0f) ? y0 : expm1f(y0);
    float act1 = (y1 > 0.0f) ? y1 : expm1f(y1);

    if (LAST) {
        ((float2*)out)[base2] = make_float2(act0, act1);
    } else {
        ((__half2*)g_Af)[base2] = __floats2half2_rn(act0, act1);
    }
}

// ---------------------------------------------------------------------------
extern "C" void kernel_launch(void* const* d_in, const int* in_sizes, int n_in,
                              void* d_out, int out_size) {
    const float* x   = (const float*)d_in[0];
    const float* Wt0 = (const float*)d_in[1];
    const float* bt0 = (const float*)d_in[2];
    const float* Wp0 = (const float*)d_in[3];
    const float* bp0 = (const float*)d_in[4];
    const float* g0  = (const float*)d_in[5];
    const float* b0  = (const float*)d_in[6];
    const float* Wt1 = (const float*)d_in[7];
    const float* bt1 = (const float*)d_in[8];
    const float* Wp1 = (const float*)d_in[9];
    const float* bp1 = (const float*)d_in[10];
    const float* g1  = (const float*)d_in[11];
    const float* b1  = (const float*)d_in[12];
    const float* Wt2 = (const float*)d_in[13];
    const float* bt2 = (const float*)d_in[14];
    const float* Wp2 = (const float*)d_in[15];
    const float* bp2 = (const float*)d_in[16];
    const float* g2  = (const float*)d_in[17];
    const float* b2  = (const float*)d_in[18];
    const int*   src = (const int*)d_in[19];
    const int*   dst = (const int*)d_in[20];
    float* out = (float*)d_out;

    // >48KB dynamic SMEM opt-in (runs immediately, not a captured node)
    cudaFuncSetAttribute(gemm_mma<DIN>, cudaFuncAttributeMaxDynamicSharedMemorySize, GEMM_SMEM);
    cudaFuncSetAttribute(gemm_mma<DH>,  cudaFuncAttributeMaxDynamicSharedMemorySize, GEMM_SMEM);

    // prep (zero cnt + all conversions) runs first; CSR build follows
    prep_kernel<<<(GN * DIN + WTOT) / 256, 256>>>(x, Wt0, Wp0, Wt1, Wp1, Wt2, Wp2);
    hist_kernel<<<EALL / 256, 256>>>(dst);
    scan_kernel<<<1, 1024>>>();
    fill_kernel<<<EALL / 256, 256>>>(src, dst);

    dim3 ggrid(GN / 128, 4);

    // Layer 0 (K = 128)
    gemm_mma<DIN><<<ggrid, 256, GEMM_SMEM>>>(LOFF0);
    fuse_kernel<false><<<GN, 128>>>(bt0, bp0, g0, b0, nullptr);

    // Layer 1 (K = 256)
    gemm_mma<DH><<<ggrid, 256, GEMM_SMEM>>>(LOFF1);
    fuse_kernel<false><<<GN, 128>>>(bt1, bp1, g1, b1, nullptr);

    // Layer 2 (K = 256), final output fp32
    gemm_mma<DH><<<ggrid, 256, GEMM_SMEM>>>(LOFF2);
    fuse_kernel<true><<<GN, 128>>>(bt2, bp2, g2, b2, out);
}